// round 10
// baseline (speedup 1.0000x reference)
#include <cuda_runtime.h>
#include <cstdint>

// GRU-GNN fused kernel for GB300 (sm_103a), v3 (resubmit; R7-R9 infra timeouts).
//   red[dst[e]] = h[src[e]]  (exactly one incoming edge per node)
//   gi = x @ w_ih^T + b_ih ; gh = red @ w_hh^T + b_hh
//   r=sig(i_r+h_r); z=sig(i_z+h_z); n=tanh(i_n + r*h_n); out=(1-z)n + z*red
//
// v3 vs v1(3370us)/v2(3822us): both prior versions were latency-bound
// (occ 12.5%, issue ~31%). v3 runs 512 threads (16 warps/SM) with v1's
// 2-row x 2-col x 6-gate blocking via a kz k-split: same load economy,
// double the latency hiding, 24 accumulators (fits 128 regs @ 512 thr).

#define MTILE 64          // edges (rows) per tile
#define CTILE 16          // output columns per tile (x6 gate blocks)
#define SP    132         // row stride in floats (split layout: [0,64)+[68,132))
#define KO    68          // float offset of the k>=64 half within a row
#define NTHREADS 512
#define GRID 152

#define WS_FLOATS (6 * CTILE * SP)   // 12672
#define XS_FLOATS (2 * MTILE * SP)   // 16896 per double-buffered array
#define SMEM_BYTES ((WS_FLOATS + 2 * XS_FLOATS) * 4 + 6 * MTILE * 4)

__device__ __forceinline__ void fma2(unsigned long long& a,
                                     unsigned long long b,
                                     unsigned long long c) {
    // packed f32x2 FMA: a.lo += b.lo*c.lo ; a.hi += b.hi*c.hi  (SASS FFMA2)
    asm("fma.rn.f32x2 %0, %1, %2, %0;" : "+l"(a) : "l"(b), "l"(c));
}

__device__ __forceinline__ float sum2(unsigned long long v) {
    float lo = __uint_as_float((unsigned)(v & 0xffffffffull));
    float hi = __uint_as_float((unsigned)(v >> 32));
    return lo + hi;
}

__device__ __forceinline__ float sigmoid_f(float t) {
    return __fdividef(1.0f, 1.0f + __expf(-t));
}

__device__ __forceinline__ void cp16(void* s, const void* g) {
    unsigned sa = (unsigned)__cvta_generic_to_shared(s);
    asm volatile("cp.async.cg.shared.global [%0], [%1], 16;" :: "r"(sa), "l"(g));
}
#define CP_COMMIT() asm volatile("cp.async.commit_group;")
#define CP_WAIT0()  asm volatile("cp.async.wait_group 0;")

// split-row float offset for float4 chunk kq (0..31): [0,64) then [68,132)
__device__ __forceinline__ int fo4(int kq) { return 4 * kq + ((kq >= 16) ? 4 : 0); }

// cp.async one (x, red) row tile: 64 rows x 512B x 2 arrays, split-row layout
__device__ __forceinline__ void issue_tile(float* XS, float* RS,
                                           const int* IDXN, const int* IDXS,
                                           const float* __restrict__ x,
                                           const float* __restrict__ h,
                                           int buf, int slot, int t) {
#pragma unroll
    for (int j = 0; j < 4; j++) {
        int f   = t + NTHREADS * j;      // 0..2047
        int row = f >> 5;                // 0..63
        int kq  = f & 31;                // float4 index along k
        int fo  = fo4(kq);
        int node = IDXN[slot * MTILE + row];
        int s    = IDXS[slot * MTILE + row];
        cp16(XS + (buf * MTILE + row) * SP + fo, x + (size_t)node * 128 + 4 * kq);
        cp16(RS + (buf * MTILE + row) * SP + fo, h + (size_t)s    * 128 + 4 * kq);
    }
}

__global__ void __launch_bounds__(NTHREADS, 1)
gru_gnn_v3_kernel(const float* __restrict__ x, const float* __restrict__ h,
                  const float* __restrict__ w_ih, const float* __restrict__ w_hh,
                  const float* __restrict__ b_ih, const float* __restrict__ b_hh,
                  const int* __restrict__ src, const int* __restrict__ dst,
                  float* __restrict__ out, int N, int num_mt, int total)
{
    extern __shared__ __align__(16) char smem_raw[];
    float* WS = (float*)smem_raw;            // weights [6][CTILE][SP], split rows
    float* XS = WS + WS_FLOATS;              // x tiles  [2][MTILE][SP]
    float* RS = XS + XS_FLOATS;              // red tiles[2][MTILE][SP]
    int* IDXN = (int*)(RS + XS_FLOATS);      // [3][MTILE] output node per row
    int* IDXS = IDXN + 3 * MTILE;            // [3][MTILE] gather src per row

    const int t  = threadIdx.x;
    const int tx = t & 7;          // cols: cg = c0 + tx + 8*ci (epilogue: ci=kz)
    const int kz = (t >> 3) & 1;   // k-half: [0,64) or [64,128)
    const int ty = t >> 4;         // 0..31 -> rows 2*ty, 2*ty+1
    const int G  = gridDim.x;

    int it0 = blockIdx.x;
    if (it0 >= total) return;

    // ---------------- prologue ----------------
    {
        int mt = it0 % num_mt;
        if (t < MTILE) {
            int e = mt * MTILE + t; if (e >= N) e = N - 1;
            IDXN[t] = dst[e];
            IDXS[t] = src[e];
        }
    }
    __syncthreads();
    issue_tile(XS, RS, IDXN, IDXS, x, h, /*buf=*/0, /*slot=*/0, t);
    CP_COMMIT();
    if (it0 + G < total) {
        int mt = (it0 + G) % num_mt;
        if (t < MTILE) {
            int e = mt * MTILE + t; if (e >= N) e = N - 1;
            IDXN[MTILE + t] = dst[e];
            IDXS[MTILE + t] = src[e];
        }
    }

    int cur_ct = -1;
    float bi0 = 0.f, bi1 = 0.f, bi2 = 0.f, bh0 = 0.f, bh1 = 0.f, bh2 = 0.f;

    // ---------------- main loop over work items (ct-major) ----------------
    for (int n = 0;; n++) {
        int it = it0 + n * G;
        if (it >= total) break;
        int buf  = n & 1;
        int slot = n % 3;
        int ct = it / num_mt;            // column tile (changes rarely)

        CP_WAIT0();                      // this tile's x/red copies retired
        __syncthreads();                 // ...visible to all; prior iter done

        bool wload = (ct != cur_ct);
        if (wload) {
            int c0 = ct * CTILE;
#pragma unroll
            for (int i = 0; i < 6; i++) {
                int f = t + NTHREADS * i;        // 3072 float4s = 6*16*32
                int rowf = f >> 5, kq = f & 31;
                int g = rowf >> 4, c = rowf & 15;
                const float* base = (g < 3) ? w_ih : w_hh;
                int g3 = (g < 3) ? g : g - 3;
                float4 v = *(const float4*)(base + ((size_t)(g3 * 128 + c0 + c)) * 128 + 4 * kq);
                *(float4*)(WS + (g * CTILE + c) * SP + fo4(kq)) = v;
            }
            int cg = c0 + tx + 8 * kz;
            bi0 = b_ih[cg];       bh0 = b_hh[cg];
            bi1 = b_ih[cg + 128]; bh1 = b_hh[cg + 128];
            bi2 = b_ih[cg + 256]; bh2 = b_hh[cg + 256];
            cur_ct = ct;
        }

        // prefetch next tile into the other buffer (overlaps compute)
        if (it + G < total) {
            issue_tile(XS, RS, IDXN, IDXS, x, h, buf ^ 1, (n + 1) % 3, t);
            CP_COMMIT();
        }
        // indices two tiles ahead (slot (n+2)%3: not read until next iter)
        if (it + 2 * G < total) {
            int mt2 = (it + 2 * G) % num_mt;
            int sl2 = (n + 2) % 3;
            if (t < MTILE) {
                int e = mt2 * MTILE + t; if (e >= N) e = N - 1;
                IDXN[sl2 * MTILE + t] = dst[e];
                IDXS[sl2 * MTILE + t] = src[e];
            }
        }
        if (wload) __syncthreads();      // weights visible before compute

        // ------- compute: 2 rows x 2 cols x 6 gates over this kz half -------
        unsigned long long acc[2][2][6];
#pragma unroll
        for (int r = 0; r < 2; r++)
#pragma unroll
            for (int ci = 0; ci < 2; ci++)
#pragma unroll
                for (int g = 0; g < 6; g++) acc[r][ci][g] = 0ull;

        const float* xb = XS + (buf * MTILE + 2 * ty) * SP + kz * KO;
        const float* rb = RS + (buf * MTILE + 2 * ty) * SP + kz * KO;
        const float* wb = WS + kz * KO;

#pragma unroll 2
        for (int k = 0; k < 64; k += 4) {
            ulonglong2 xv0 = *(const ulonglong2*)(xb + k);
            ulonglong2 xv1 = *(const ulonglong2*)(xb + SP + k);
            ulonglong2 rv0 = *(const ulonglong2*)(rb + k);
            ulonglong2 rv1 = *(const ulonglong2*)(rb + SP + k);
#pragma unroll
            for (int g = 0; g < 6; g++) {
                ulonglong2 a0 = (g < 3) ? xv0 : rv0;   // compile-time select
                ulonglong2 a1 = (g < 3) ? xv1 : rv1;
#pragma unroll
                for (int ci = 0; ci < 2; ci++) {
                    ulonglong2 wv = *(const ulonglong2*)(
                        wb + (g * CTILE + tx + 8 * ci) * SP + k);
                    fma2(acc[0][ci][g], wv.x, a0.x);
                    fma2(acc[0][ci][g], wv.y, a0.y);
                    fma2(acc[1][ci][g], wv.x, a1.x);
                    fma2(acc[1][ci][g], wv.y, a1.y);
                }
            }
        }

        // ------- combine kz halves + GRU epilogue (1 col per thread) -------
        int c0 = ct * CTILE;
        int cg = c0 + tx + 8 * kz;
        int co = cg + ((cg >= 64) ? 4 : 0);   // split-row offset of element cg
#pragma unroll
        for (int r = 0; r < 2; r++) {
            float s[6];
#pragma unroll
            for (int g = 0; g < 6; g++) {
                float skeep = sum2(acc[r][kz][g]);      // my half, my col
                float ssend = sum2(acc[r][kz ^ 1][g]);  // my half, partner col
                float recv  = __shfl_xor_sync(0xffffffffu, ssend, 8);
                s[g] = skeep + recv;                    // full-k sum for col cg
            }
            int row  = 2 * ty + r;
            int node = IDXN[slot * MTILE + row];
            float gr = s[0] + bi0, gz = s[1] + bi1, gn = s[2] + bi2;
            float hr = s[3] + bh0, hz = s[4] + bh1, hn = s[5] + bh2;
            float rg = sigmoid_f(gr + hr);
            float zg = sigmoid_f(gz + hz);
            float ng = tanhf(gn + rg * hn);
            float red = RS[(buf * MTILE + row) * SP + co];
            out[(size_t)node * 128 + cg] = (1.0f - zg) * ng + zg * red;
        }
    }
}

extern "C" void kernel_launch(void* const* d_in, const int* in_sizes, int n_in,
                              void* d_out, int out_size) {
    const float* x    = (const float*)d_in[0];
    const float* h    = (const float*)d_in[1];
    const float* w_ih = (const float*)d_in[2];
    const float* w_hh = (const float*)d_in[3];
    const float* b_ih = (const float*)d_in[4];
    const float* b_hh = (const float*)d_in[5];
    const int*   src  = (const int*)d_in[6];
    const int*   dst  = (const int*)d_in[7];
    float* out = (float*)d_out;

    int N = in_sizes[6];                 // #edges == #nodes
    int num_mt = (N + MTILE - 1) / MTILE;
    int total  = (128 / CTILE) * num_mt; // 8 column tiles

    cudaFuncSetAttribute(gru_gnn_v3_kernel,
                         cudaFuncAttributeMaxDynamicSharedMemorySize, SMEM_BYTES);

    int grid = GRID < total ? GRID : total;
    gru_gnn_v3_kernel<<<grid, NTHREADS, SMEM_BYTES>>>(
        x, h, w_ih, w_hh, b_ih, b_hh, src, dst, out, N, num_mt, total);
}

// round 14
// speedup vs baseline: 1.6076x; 1.6076x over previous
#include <cuda_runtime.h>
#include <cstdint>

// GRU-GNN fused kernel for GB300 (sm_103a), v4 (resubmit; R11-R13 infra timeouts).
//   red[dst[e]] = h[src[e]]  (exactly one incoming edge per node)
//   gi = x @ w_ih^T + b_ih ; gh = red @ w_hh^T + b_hh
//   r=sig(i_r+h_r); z=sig(i_z+h_z); n=tanh(i_n + r*h_n); out=(1-z)n + z*red
//
// v4 vs v1(3370)/v2(3822)/v3(4220): all were smem-INSTRUCTION-bound
// (LDS.128 = 4 crossbar phases each; 4096 LDS/item = 16384 cyc >> 6144 FMA
// cyc; model matches v3's L1 time within 1%). v4 halves n_LDS via a gate
// split: each thread handles 3 gates (ih OR hh) so it reads ONE activation
// array, enabling 4 rows x 4 cols blocking: 96 FFMA2 : 16 LDS per warp-step
// -> 2048 LDS/item = 8192 crossbar cyc, near the 6144-cyc FMA floor.
// Lanes: tx(4 cols) x gs(gate half) x kz(k half) x ty(16 row groups);
// bank-padded layouts keep every phase conflict-free; kz/gs halves
// recombine with 60 shfl per item.

#define MTILE 64            // edges (rows) per tile
#define CTILE 16            // output columns per tile
#define SP    132           // row stride in floats (split k: [0,64)+[68,132))
#define KO    68            // float offset of the k>=64 half within a row
#define WGS   (CTILE*SP+16) // 2128: gate-block stride (pad -> gs phases disjoint)
#define NTHREADS 256
#define GRID 152

#define WS_FLOATS (6 * WGS)          // 12768
#define XS_FLOATS (2 * MTILE * SP)   // 16896 per double-buffered array
// RS offset by +16 floats so x vs red lanes hit disjoint banks in a phase
#define SMEM_BYTES ((WS_FLOATS + 2 * XS_FLOATS + 16) * 4 + 6 * MTILE * 4)

__device__ __forceinline__ void fma2(unsigned long long& a,
                                     unsigned long long b,
                                     unsigned long long c) {
    // packed f32x2 FMA: a.lo += b.lo*c.lo ; a.hi += b.hi*c.hi  (SASS FFMA2)
    asm("fma.rn.f32x2 %0, %1, %2, %0;" : "+l"(a) : "l"(b), "l"(c));
}

__device__ __forceinline__ float sum2(unsigned long long v) {
    float lo = __uint_as_float((unsigned)(v & 0xffffffffull));
    float hi = __uint_as_float((unsigned)(v >> 32));
    return lo + hi;
}

__device__ __forceinline__ float sigmoid_f(float t) {
    return __fdividef(1.0f, 1.0f + __expf(-t));
}

__device__ __forceinline__ void cp16(void* s, const void* g) {
    unsigned sa = (unsigned)__cvta_generic_to_shared(s);
    asm volatile("cp.async.cg.shared.global [%0], [%1], 16;" :: "r"(sa), "l"(g));
}
#define CP_COMMIT() asm volatile("cp.async.commit_group;")
#define CP_WAIT0()  asm volatile("cp.async.wait_group 0;")

// split-row float offset for float4 chunk kq (0..31): [0,64) then [68,132)
__device__ __forceinline__ int fo4(int kq) { return 4 * kq + ((kq >= 16) ? 4 : 0); }

// cp.async one (x, red) row tile: 64 rows x 512B x 2 arrays, split-row layout
__device__ __forceinline__ void issue_tile(float* XS, float* RS,
                                           const int* IDXN, const int* IDXS,
                                           const float* __restrict__ x,
                                           const float* __restrict__ h,
                                           int buf, int slot, int t) {
#pragma unroll
    for (int j = 0; j < 8; j++) {
        int f   = t + NTHREADS * j;      // 0..2047
        int row = f >> 5;                // 0..63
        int kq  = f & 31;                // float4 index along k
        int fo  = fo4(kq);
        int node = IDXN[slot * MTILE + row];
        int s    = IDXS[slot * MTILE + row];
        cp16(XS + (buf * MTILE + row) * SP + fo, x + (size_t)node * 128 + 4 * kq);
        cp16(RS + (buf * MTILE + row) * SP + fo, h + (size_t)s    * 128 + 4 * kq);
    }
}

__global__ void __launch_bounds__(NTHREADS, 1)
gru_gnn_v4_kernel(const float* __restrict__ x, const float* __restrict__ h,
                  const float* __restrict__ w_ih, const float* __restrict__ w_hh,
                  const float* __restrict__ b_ih, const float* __restrict__ b_hh,
                  const int* __restrict__ src, const int* __restrict__ dst,
                  float* __restrict__ out, int N, int num_mt, int total)
{
    extern __shared__ __align__(16) char smem_raw[];
    float* WS = (float*)smem_raw;              // weights [6][WGS] gate-padded
    float* XS = WS + WS_FLOATS;                // x tiles  [2][MTILE][SP]
    float* RS = XS + XS_FLOATS + 16;           // red tiles (bank-offset +16)
    int* IDXN = (int*)(RS + XS_FLOATS);        // [3][MTILE] output node per row
    int* IDXS = IDXN + 3 * MTILE;              // [3][MTILE] gather src per row

    const int t  = threadIdx.x;
    const int tx = t & 3;          // cols: cg = c0 + tx + 4*ci
    const int gs = (t >> 2) & 1;   // 0: ih gates (x), 1: hh gates (red)
    const int kz = (t >> 3) & 1;   // k-half: [0,64) or [64,128)
    const int ty = t >> 4;         // 0..15 -> rows 4*ty .. 4*ty+3
    const int G  = gridDim.x;

    int it0 = blockIdx.x;
    if (it0 >= total) return;

    // ---------------- prologue ----------------
    {
        int mt = it0 % num_mt;
        if (t < MTILE) {
            int e = mt * MTILE + t; if (e >= N) e = N - 1;
            IDXN[t] = dst[e];
            IDXS[t] = src[e];
        }
    }
    __syncthreads();
    issue_tile(XS, RS, IDXN, IDXS, x, h, /*buf=*/0, /*slot=*/0, t);
    CP_COMMIT();
    if (it0 + G < total) {
        int mt = (it0 + G) % num_mt;
        if (t < MTILE) {
            int e = mt * MTILE + t; if (e >= N) e = N - 1;
            IDXN[MTILE + t] = dst[e];
            IDXS[MTILE + t] = src[e];
        }
    }

    const int kept = gs ? 2 : 0;   // final ci pair this thread outputs
    const int comp = gs ? 0 : 2;   // ci pair sent to the gs partner
    int cur_ct = -1;
    float bi[3][2], bh[3][2];
#pragma unroll
    for (int j = 0; j < 3; j++) bi[j][0] = bi[j][1] = bh[j][0] = bh[j][1] = 0.f;

    // ---------------- main loop over work items (ct-major) ----------------
    for (int n = 0;; n++) {
        int it = it0 + n * G;
        if (it >= total) break;
        int buf  = n & 1;
        int slot = n % 3;
        int ct = it / num_mt;            // column tile (changes rarely)

        CP_WAIT0();                      // this tile's x/red copies retired
        __syncthreads();                 // ...visible to all; prior iter done

        bool wload = (ct != cur_ct);
        if (wload) {
            int c0 = ct * CTILE;
#pragma unroll
            for (int i = 0; i < 12; i++) {
                int f = t + NTHREADS * i;        // 3072 float4s = 6*16*32
                int rowf = f >> 5, kq = f & 31;
                int g = rowf >> 4, c = rowf & 15;
                const float* base = (g < 3) ? w_ih : w_hh;
                int g3 = (g < 3) ? g : g - 3;
                float4 v = *(const float4*)(base + ((size_t)(g3 * 128 + c0 + c)) * 128 + 4 * kq);
                *(float4*)(WS + g * WGS + c * SP + fo4(kq)) = v;
            }
#pragma unroll
            for (int s = 0; s < 2; s++) {
                int cgb = c0 + tx + 4 * (kept + s);
                bi[0][s] = b_ih[cgb];       bh[0][s] = b_hh[cgb];
                bi[1][s] = b_ih[cgb + 128]; bh[1][s] = b_hh[cgb + 128];
                bi[2][s] = b_ih[cgb + 256]; bh[2][s] = b_hh[cgb + 256];
            }
            cur_ct = ct;
        }

        // prefetch next tile into the other buffer (overlaps compute)
        if (it + G < total) {
            issue_tile(XS, RS, IDXN, IDXS, x, h, buf ^ 1, (n + 1) % 3, t);
            CP_COMMIT();
        }
        // indices two tiles ahead (slot (n+2)%3: not read until next iter)
        if (it + 2 * G < total) {
            int mt2 = (it + 2 * G) % num_mt;
            int sl2 = (n + 2) % 3;
            if (t < MTILE) {
                int e = mt2 * MTILE + t; if (e >= N) e = N - 1;
                IDXN[sl2 * MTILE + t] = dst[e];
                IDXS[sl2 * MTILE + t] = src[e];
            }
        }
        if (wload) __syncthreads();      // weights visible before compute

        // ---- compute: 3 gates x 4 rows x 4 cols over this (gs, kz) part ----
        unsigned long long acc[3][4][4];
#pragma unroll
        for (int j = 0; j < 3; j++)
#pragma unroll
            for (int r = 0; r < 4; r++)
#pragma unroll
                for (int ci = 0; ci < 4; ci++) acc[j][r][ci] = 0ull;

        const float* ab = (gs ? RS : XS) + (buf * MTILE + 4 * ty) * SP + kz * KO;
        const float* wb = WS + 3 * gs * WGS + tx * SP + kz * KO;

#pragma unroll 2
        for (int k = 0; k < 64; k += 4) {
            ulonglong2 av[4];
#pragma unroll
            for (int r = 0; r < 4; r++)
                av[r] = *(const ulonglong2*)(ab + r * SP + k);
#pragma unroll
            for (int j = 0; j < 3; j++) {
#pragma unroll
                for (int ci = 0; ci < 4; ci++) {
                    ulonglong2 wv = *(const ulonglong2*)(
                        wb + j * WGS + 4 * ci * SP + k);
#pragma unroll
                    for (int r = 0; r < 4; r++) {
                        fma2(acc[j][r][ci], wv.x, av[r].x);
                        fma2(acc[j][r][ci], wv.y, av[r].y);
                    }
                }
            }
        }

        // ---- combine kz halves (48 shfl), exchange gate halves (12 shfl) ----
        float fsum[3][4][4];
#pragma unroll
        for (int j = 0; j < 3; j++)
#pragma unroll
            for (int r = 0; r < 4; r++)
#pragma unroll
                for (int ci = 0; ci < 4; ci++) {
                    float p = sum2(acc[j][r][ci]);
                    fsum[j][r][ci] = p + __shfl_xor_sync(0xffffffffu, p, 8);
                }

        float oth[3][2][2];    // partner's gate triple for my rows/cols
#pragma unroll
        for (int j = 0; j < 3; j++)
#pragma unroll
            for (int r2 = 0; r2 < 2; r2++)
#pragma unroll
                for (int s = 0; s < 2; s++)
                    oth[j][r2][s] = __shfl_xor_sync(
                        0xffffffffu, fsum[j][2 * kz + r2][comp + s], 4);

        // ---- GRU epilogue: 2 rows (kz-split) x 2 cols per thread ----
        int c0 = ct * CTILE;
#pragma unroll
        for (int r2 = 0; r2 < 2; r2++) {
            int r    = 2 * kz + r2;
            int row  = 4 * ty + r;
            int node = IDXN[slot * MTILE + row];
#pragma unroll
            for (int s = 0; s < 2; s++) {
                int cg = c0 + tx + 4 * (kept + s);
                float a0 = fsum[0][r][kept + s];
                float a1 = fsum[1][r][kept + s];
                float a2 = fsum[2][r][kept + s];
                float o0 = oth[0][r2][s], o1 = oth[1][r2][s], o2 = oth[2][r2][s];
                float gr = gs ? o0 : a0, hr = gs ? a0 : o0;
                float gz = gs ? o1 : a1, hz = gs ? a1 : o1;
                float gn = gs ? o2 : a2, hn = gs ? a2 : o2;
                float rg = sigmoid_f((gr + bi[0][s]) + (hr + bh[0][s]));
                float zg = sigmoid_f((gz + bi[1][s]) + (hz + bh[1][s]));
                float ng = tanhf((gn + bi[2][s]) + rg * (hn + bh[2][s]));
                float red = RS[(buf * MTILE + row) * SP + cg + ((cg >= 64) ? 4 : 0)];
                out[(size_t)node * 128 + cg] = (1.0f - zg) * ng + zg * red;
            }
        }
    }
}

extern "C" void kernel_launch(void* const* d_in, const int* in_sizes, int n_in,
                              void* d_out, int out_size) {
    const float* x    = (const float*)d_in[0];
    const float* h    = (const float*)d_in[1];
    const float* w_ih = (const float*)d_in[2];
    const float* w_hh = (const float*)d_in[3];
    const float* b_ih = (const float*)d_in[4];
    const float* b_hh = (const float*)d_in[5];
    const int*   src  = (const int*)d_in[6];
    const int*   dst  = (const int*)d_in[7];
    float* out = (float*)d_out;

    int N = in_sizes[6];                 // #edges == #nodes
    int num_mt = (N + MTILE - 1) / MTILE;
    int total  = (128 / CTILE) * num_mt; // 8 column tiles

    cudaFuncSetAttribute(gru_gnn_v4_kernel,
                         cudaFuncAttributeMaxDynamicSharedMemorySize, SMEM_BYTES);

    int grid = GRID < total ? GRID : total;
    gru_gnn_v4_kernel<<<grid, NTHREADS, SMEM_BYTES>>>(
        x, h, w_ih, w_hh, b_ih, b_hh, src, dst, out, N, num_mt, total);
}